// round 1
// baseline (speedup 1.0000x reference)
#include <cuda_runtime.h>

#define BH 64
#define SEQ 8192
#define D 64
#define SPLITS 16
#define ROWS_PER_SPLIT (SEQ / SPLITS)   // 512
#define CHUNK 8
#define PART_STRIDE (D * D + D)         // 4160 floats: numer[4096] + z[64]

// Scratch (device globals — no allocation allowed)
__device__ float g_part[BH * SPLITS * PART_STRIDE];  // ~17 MB
__device__ float g_ctx[BH * D * D];                  // normalized context

// ---------------- f32x2 helpers ----------------
__device__ __forceinline__ unsigned long long pack2(float x, float y) {
    unsigned long long r;
    asm("mov.b64 %0, {%1, %2};" : "=l"(r) : "f"(x), "f"(y));
    return r;
}
__device__ __forceinline__ void fma2(unsigned long long& acc,
                                     unsigned long long a,
                                     unsigned long long b) {
    asm("fma.rn.f32x2 %0, %1, %2, %0;" : "+l"(acc) : "l"(a), "l"(b));
}
__device__ __forceinline__ void unpack2(unsigned long long v, float& x, float& y) {
    asm("mov.b64 {%0, %1}, %2;" : "=f"(x), "=f"(y) : "l"(v));
}

// ---------------- Kernel 1: partial context (exp(K)^T @ V and column sums) ----------------
// grid (BH, SPLITS), 256 threads. Each CTA: 512 rows, 4x4 register microtile per thread.
__global__ void __launch_bounds__(256) ctx_partial_kernel(
    const float* __restrict__ k, const float* __restrict__ v) {
    const int head  = blockIdx.x;
    const int split = blockIdx.y;
    const size_t base = (size_t)head * SEQ * D + (size_t)split * ROWS_PER_SPLIT * D;
    const float* kb = k + base;
    const float* vb = v + base;

    __shared__ float ek[CHUNK][D];
    __shared__ float vv[CHUNK][D];

    const int tid = threadIdx.x;
    const int tx = tid & 15;   // e-group
    const int ty = tid >> 4;   // d-group

    unsigned long long acc[4][2];
#pragma unroll
    for (int i = 0; i < 4; i++) { acc[i][0] = 0ULL; acc[i][1] = 0ULL; }
    float zacc = 0.0f;

    for (int row0 = 0; row0 < ROWS_PER_SPLIT; row0 += CHUNK) {
        // stage CHUNK rows of exp(k) and v
        if (tid < 128) {
            int r = tid >> 4, c = (tid & 15) * 4;
            float4 kv = *(const float4*)&kb[(row0 + r) * D + c];
            ek[r][c + 0] = __expf(kv.x);
            ek[r][c + 1] = __expf(kv.y);
            ek[r][c + 2] = __expf(kv.z);
            ek[r][c + 3] = __expf(kv.w);
        } else {
            int t = tid - 128;
            int r = t >> 4, c = (t & 15) * 4;
            *(float4*)&vv[r][c] = *(const float4*)&vb[(row0 + r) * D + c];
        }
        __syncthreads();

#pragma unroll
        for (int r = 0; r < CHUNK; r++) {
            float4 e4 = *(const float4*)&ek[r][ty << 2];
            float4 v4 = *(const float4*)&vv[r][tx << 2];
            unsigned long long b0 = pack2(v4.x, v4.y);
            unsigned long long b1 = pack2(v4.z, v4.w);
            unsigned long long a;
            a = pack2(e4.x, e4.x); fma2(acc[0][0], a, b0); fma2(acc[0][1], a, b1);
            a = pack2(e4.y, e4.y); fma2(acc[1][0], a, b0); fma2(acc[1][1], a, b1);
            a = pack2(e4.z, e4.z); fma2(acc[2][0], a, b0); fma2(acc[2][1], a, b1);
            a = pack2(e4.w, e4.w); fma2(acc[3][0], a, b0); fma2(acc[3][1], a, b1);
        }
        // column sums of exp(k) for Z (warps 0-1 only)
        if (tid < D) {
#pragma unroll
            for (int r = 0; r < CHUNK; r++) zacc += ek[r][tid];
        }
        __syncthreads();
    }

    float* np = g_part + ((size_t)(head * SPLITS + split)) * PART_STRIDE;
#pragma unroll
    for (int i = 0; i < 4; i++) {
        int d = ty * 4 + i;
        float x0, x1, x2, x3;
        unpack2(acc[i][0], x0, x1);
        unpack2(acc[i][1], x2, x3);
        float4 o = make_float4(x0, x1, x2, x3);
        *(float4*)&np[d * D + tx * 4] = o;
    }
    if (tid < D) np[D * D + tid] = zacc;
}

// ---------------- Kernel 2: reduce splits + normalize -> g_ctx ----------------
__global__ void __launch_bounds__(256) reduce_ctx_kernel() {
    const int head = blockIdx.x;
    const int tid = threadIdx.x;
    __shared__ float zs[D];
    const float* pb = g_part + (size_t)head * SPLITS * PART_STRIDE;

    if (tid < D) {
        float s = 0.0f;
#pragma unroll
        for (int sp = 0; sp < SPLITS; sp++) s += pb[sp * PART_STRIDE + D * D + tid];
        zs[tid] = 1.0f / s;
    }
    __syncthreads();

    for (int i = tid; i < D * D; i += 256) {
        float s = 0.0f;
#pragma unroll
        for (int sp = 0; sp < SPLITS; sp++) s += pb[sp * PART_STRIDE + i];
        g_ctx[head * D * D + i] = s * zs[i >> 6];
    }
}

// ---------------- Kernel 3: out = (softmax_ch(q)*scale) @ ctx ----------------
// grid (BH, SEQ/64), 256 threads; 64-row tile; 4x4 microtile, f32x2 accumulators.
#define PT_STRIDE 68   // padded row stride for transposed exp(q); 68*4B % 16 == 0
__global__ void __launch_bounds__(256) out_kernel(
    const float* __restrict__ q, float* __restrict__ out) {
    const int head = blockIdx.x;
    const int tile = blockIdx.y;
    const int tid = threadIdx.x;

    __shared__ float ctx[D][D];          // 16 KB
    __shared__ float pT[D][PT_STRIDE];   // exp(q) transposed, padded
    __shared__ float sinv[D];            // scale / rowsum

    // load context for this head
    {
        const float4* src = (const float4*)(g_ctx + (size_t)head * D * D);
        float4* dst = (float4*)&ctx[0][0];
        for (int i = tid; i < (D * D) / 4; i += 256) dst[i] = src[i];
    }

    const float* qb = q + (size_t)head * SEQ * D + (size_t)tile * 64 * D;
    // stage exp(q) transposed
    for (int i = tid; i < 1024; i += 256) {   // 1024 float4s = 64 rows x 16
        int r = i >> 4, c = (i & 15) * 4;
        float4 qv = *(const float4*)&qb[r * D + c];
        pT[c + 0][r] = __expf(qv.x);
        pT[c + 1][r] = __expf(qv.y);
        pT[c + 2][r] = __expf(qv.z);
        pT[c + 3][r] = __expf(qv.w);
    }
    __syncthreads();

    if (tid < D) {
        float ss = 0.0f;
#pragma unroll
        for (int d = 0; d < D; d++) ss += pT[d][tid];
        sinv[tid] = 0.125f / ss;   // scale = 1/sqrt(64) folded in
    }
    __syncthreads();

    const int tx = tid & 15;   // e-group
    const int ty = tid >> 4;   // row-group
    unsigned long long acc[4][2];
#pragma unroll
    for (int i = 0; i < 4; i++) { acc[i][0] = 0ULL; acc[i][1] = 0ULL; }

#pragma unroll 8
    for (int d = 0; d < D; d++) {
        float4 p4 = *(const float4*)&pT[d][ty << 2];
        float4 c4 = *(const float4*)&ctx[d][tx << 2];
        unsigned long long b0 = pack2(c4.x, c4.y);
        unsigned long long b1 = pack2(c4.z, c4.w);
        unsigned long long a;
        a = pack2(p4.x, p4.x); fma2(acc[0][0], a, b0); fma2(acc[0][1], a, b1);
        a = pack2(p4.y, p4.y); fma2(acc[1][0], a, b0); fma2(acc[1][1], a, b1);
        a = pack2(p4.z, p4.z); fma2(acc[2][0], a, b0); fma2(acc[2][1], a, b1);
        a = pack2(p4.w, p4.w); fma2(acc[3][0], a, b0); fma2(acc[3][1], a, b1);
    }

    float* ob = out + (size_t)head * SEQ * D + (size_t)tile * 64 * D;
#pragma unroll
    for (int i = 0; i < 4; i++) {
        int r = ty * 4 + i;
        float f = sinv[r];
        float x0, x1, x2, x3;
        unpack2(acc[i][0], x0, x1);
        unpack2(acc[i][1], x2, x3);
        float4 o = make_float4(x0 * f, x1 * f, x2 * f, x3 * f);
        *(float4*)&ob[r * D + tx * 4] = o;
    }
}

// ---------------- launch ----------------
extern "C" void kernel_launch(void* const* d_in, const int* in_sizes, int n_in,
                              void* d_out, int out_size) {
    const float* q = (const float*)d_in[0];
    const float* k = (const float*)d_in[1];
    const float* v = (const float*)d_in[2];
    float* out = (float*)d_out;
    (void)in_sizes; (void)n_in; (void)out_size;

    dim3 gridB(BH, SPLITS);
    ctx_partial_kernel<<<gridB, 256>>>(k, v);
    reduce_ctx_kernel<<<BH, 256>>>();
    dim3 gridD(BH, SEQ / 64);
    out_kernel<<<gridD, 256>>>(q, out);
}

// round 2
// speedup vs baseline: 1.5297x; 1.5297x over previous
#include <cuda_runtime.h>

#define BH 64
#define SEQ 8192
#define D 64
#define SPLITS 16
#define ROWS_PER_SPLIT (SEQ / SPLITS)   // 512
#define CHUNK 8
#define PART_STRIDE (D * D + D)         // 4160 floats: numer[4096] + z[64]

// Scratch (device globals — no allocation allowed)
__device__ float g_part[BH * SPLITS * PART_STRIDE];  // ~17 MB
__device__ float g_ctx[BH * D * D];                  // normalized context

// ---------------- f32x2 helpers ----------------
__device__ __forceinline__ unsigned long long pack2(float x, float y) {
    unsigned long long r;
    asm("mov.b64 %0, {%1, %2};" : "=l"(r) : "f"(x), "f"(y));
    return r;
}
__device__ __forceinline__ void fma2(unsigned long long& acc,
                                     unsigned long long a,
                                     unsigned long long b) {
    asm("fma.rn.f32x2 %0, %1, %2, %0;" : "+l"(acc) : "l"(a), "l"(b));
}
__device__ __forceinline__ void unpack2(unsigned long long v, float& x, float& y) {
    asm("mov.b64 {%0, %1}, %2;" : "=f"(x), "=f"(y) : "l"(v));
}

// ---------------- Kernel 1: partial context (exp(K)^T @ V and column sums) ----------------
// grid (BH, SPLITS), 256 threads. Each CTA: 512 rows, 4x4 register microtile per thread.
__global__ void __launch_bounds__(256) ctx_partial_kernel(
    const float* __restrict__ k, const float* __restrict__ v) {
    const int head  = blockIdx.x;
    const int split = blockIdx.y;
    const size_t base = (size_t)head * SEQ * D + (size_t)split * ROWS_PER_SPLIT * D;
    const float* kb = k + base;
    const float* vb = v + base;

    __shared__ float ek[CHUNK][D];
    __shared__ float vv[CHUNK][D];

    const int tid = threadIdx.x;
    const int tx = tid & 15;   // e-group
    const int ty = tid >> 4;   // d-group

    unsigned long long acc[4][2];
#pragma unroll
    for (int i = 0; i < 4; i++) { acc[i][0] = 0ULL; acc[i][1] = 0ULL; }
    float zacc = 0.0f;

    for (int row0 = 0; row0 < ROWS_PER_SPLIT; row0 += CHUNK) {
        // stage CHUNK rows of exp(k) and v
        if (tid < 128) {
            int r = tid >> 4, c = (tid & 15) * 4;
            float4 kv = *(const float4*)&kb[(row0 + r) * D + c];
            ek[r][c + 0] = __expf(kv.x);
            ek[r][c + 1] = __expf(kv.y);
            ek[r][c + 2] = __expf(kv.z);
            ek[r][c + 3] = __expf(kv.w);
        } else {
            int t = tid - 128;
            int r = t >> 4, c = (t & 15) * 4;
            *(float4*)&vv[r][c] = *(const float4*)&vb[(row0 + r) * D + c];
        }
        __syncthreads();

#pragma unroll
        for (int r = 0; r < CHUNK; r++) {
            float4 e4 = *(const float4*)&ek[r][ty << 2];
            float4 v4 = *(const float4*)&vv[r][tx << 2];
            unsigned long long b0 = pack2(v4.x, v4.y);
            unsigned long long b1 = pack2(v4.z, v4.w);
            unsigned long long a;
            a = pack2(e4.x, e4.x); fma2(acc[0][0], a, b0); fma2(acc[0][1], a, b1);
            a = pack2(e4.y, e4.y); fma2(acc[1][0], a, b0); fma2(acc[1][1], a, b1);
            a = pack2(e4.z, e4.z); fma2(acc[2][0], a, b0); fma2(acc[2][1], a, b1);
            a = pack2(e4.w, e4.w); fma2(acc[3][0], a, b0); fma2(acc[3][1], a, b1);
        }
        // column sums of exp(k) for Z (warps 0-1 only)
        if (tid < D) {
#pragma unroll
            for (int r = 0; r < CHUNK; r++) zacc += ek[r][tid];
        }
        __syncthreads();
    }

    float* np = g_part + ((size_t)(head * SPLITS + split)) * PART_STRIDE;
#pragma unroll
    for (int i = 0; i < 4; i++) {
        int d = ty * 4 + i;
        float x0, x1, x2, x3;
        unpack2(acc[i][0], x0, x1);
        unpack2(acc[i][1], x2, x3);
        float4 o = make_float4(x0, x1, x2, x3);
        *(float4*)&np[d * D + tx * 4] = o;
    }
    if (tid < D) np[D * D + tid] = zacc;
}

// ---------------- Kernel 2: reduce splits + normalize -> g_ctx ----------------
__global__ void __launch_bounds__(256) reduce_ctx_kernel() {
    const int head = blockIdx.x;
    const int tid = threadIdx.x;
    __shared__ float zs[D];
    const float* pb = g_part + (size_t)head * SPLITS * PART_STRIDE;

    if (tid < D) {
        float s = 0.0f;
#pragma unroll
        for (int sp = 0; sp < SPLITS; sp++) s += pb[sp * PART_STRIDE + D * D + tid];
        zs[tid] = 1.0f / s;
    }
    __syncthreads();

    for (int i = tid; i < D * D; i += 256) {
        float s = 0.0f;
#pragma unroll
        for (int sp = 0; sp < SPLITS; sp++) s += pb[sp * PART_STRIDE + i];
        g_ctx[head * D * D + i] = s * zs[i >> 6];
    }
}

// ---------------- Kernel 3: out = (softmax_ch(q)*scale) @ ctx ----------------
// grid (BH, SEQ/64), 256 threads; 64-row tile; 4x4 microtile, f32x2 accumulators.
#define PT_STRIDE 68   // padded row stride for transposed exp(q); 68*4B % 16 == 0
__global__ void __launch_bounds__(256) out_kernel(
    const float* __restrict__ q, float* __restrict__ out) {
    const int head = blockIdx.x;
    const int tile = blockIdx.y;
    const int tid = threadIdx.x;

    __shared__ float ctx[D][D];          // 16 KB
    __shared__ float pT[D][PT_STRIDE];   // exp(q) transposed, padded
    __shared__ float sinv[D];            // scale / rowsum

    // load context for this head
    {
        const float4* src = (const float4*)(g_ctx + (size_t)head * D * D);
        float4* dst = (float4*)&ctx[0][0];
        for (int i = tid; i < (D * D) / 4; i += 256) dst[i] = src[i];
    }

    const float* qb = q + (size_t)head * SEQ * D + (size_t)tile * 64 * D;
    // stage exp(q) transposed
    for (int i = tid; i < 1024; i += 256) {   // 1024 float4s = 64 rows x 16
        int r = i >> 4, c = (i & 15) * 4;
        float4 qv = *(const float4*)&qb[r * D + c];
        pT[c + 0][r] = __expf(qv.x);
        pT[c + 1][r] = __expf(qv.y);
        pT[c + 2][r] = __expf(qv.z);
        pT[c + 3][r] = __expf(qv.w);
    }
    __syncthreads();

    if (tid < D) {
        float ss = 0.0f;
#pragma unroll
        for (int d = 0; d < D; d++) ss += pT[d][tid];
        sinv[tid] = 0.125f / ss;   // scale = 1/sqrt(64) folded in
    }
    __syncthreads();

    const int tx = tid & 15;   // e-group
    const int ty = tid >> 4;   // row-group
    unsigned long long acc[4][2];
#pragma unroll
    for (int i = 0; i < 4; i++) { acc[i][0] = 0ULL; acc[i][1] = 0ULL; }

#pragma unroll 8
    for (int d = 0; d < D; d++) {
        float4 p4 = *(const float4*)&pT[d][ty << 2];
        float4 c4 = *(const float4*)&ctx[d][tx << 2];
        unsigned long long b0 = pack2(c4.x, c4.y);
        unsigned long long b1 = pack2(c4.z, c4.w);
        unsigned long long a;
        a = pack2(p4.x, p4.x); fma2(acc[0][0], a, b0); fma2(acc[0][1], a, b1);
        a = pack2(p4.y, p4.y); fma2(acc[1][0], a, b0); fma2(acc[1][1], a, b1);
        a = pack2(p4.z, p4.z); fma2(acc[2][0], a, b0); fma2(acc[2][1], a, b1);
        a = pack2(p4.w, p4.w); fma2(acc[3][0], a, b0); fma2(acc[3][1], a, b1);
    }

    float* ob = out + (size_t)head * SEQ * D + (size_t)tile * 64 * D;
#pragma unroll
    for (int i = 0; i < 4; i++) {
        int r = ty * 4 + i;
        float f = sinv[r];
        float x0, x1, x2, x3;
        unpack2(acc[i][0], x0, x1);
        unpack2(acc[i][1], x2, x3);
        float4 o = make_float4(x0 * f, x1 * f, x2 * f, x3 * f);
        *(float4*)&ob[r * D + tx * 4] = o;
    }
}

// ---------------- launch ----------------
extern "C" void kernel_launch(void* const* d_in, const int* in_sizes, int n_in,
                              void* d_out, int out_size) {
    const float* q = (const float*)d_in[0];
    const float* k = (const float*)d_in[1];
    const float* v = (const float*)d_in[2];
    float* out = (float*)d_out;
    (void)in_sizes; (void)n_in; (void)out_size;

    dim3 gridB(BH, SPLITS);
    ctx_partial_kernel<<<gridB, 256>>>(k, v);
    reduce_ctx_kernel<<<BH, 256>>>();
    dim3 gridD(BH, SEQ / 64);
    out_kernel<<<gridD, 256>>>(q, out);
}